// round 2
// baseline (speedup 1.0000x reference)
#include <cuda_runtime.h>
#include <math.h>

// Problem constants
#define Bz     2
#define SEQ    2048
#define EMB    1024
#define NHEAD  16
#define HDIM   64
#define HIDDEN 4096
#define TOK    (Bz * SEQ)          // 4096 rows
#define BH     (Bz * NHEAD)        // 32 batched heads

// -------- scratch (static device globals; no allocation allowed) ----------
__device__ float g_ln1   [TOK * EMB];          // 16 MB
__device__ float g_qkv   [TOK * 3 * EMB];      // 48 MB
__device__ float g_q     [BH * SEQ * HDIM];    // 16 MB
__device__ float g_k     [BH * SEQ * HDIM];    // 16 MB
__device__ float g_v     [BH * SEQ * HDIM];    // 16 MB
__device__ float g_scores[(long long)BH * SEQ * SEQ]; // 512 MB
__device__ float g_attn  [BH * SEQ * HDIM];    // 16 MB  (b,h,n,d)
__device__ float g_attnm [TOK * EMB];          // 16 MB  (b,n,h*d)
__device__ float g_x1    [TOK * EMB];          // 16 MB  residual after attn
__device__ float g_ln2   [TOK * EMB];          // 16 MB
__device__ float g_h     [TOK * HIDDEN];       // 64 MB

// ---------------------------- GEMM -----------------------------------
// C[M,N] = alpha * A[M,K] @ op(B) (+ bias[n]) (+ resid) (gelu)
// TRANSB=0: B is KxN row-major.  TRANSB=1: B is NxK row-major (C = A B^T).
// EPI: 0 none, 1 +bias, 2 +bias+resid, 3 gelu(+bias)
__device__ __forceinline__ float gelu_exact(float x) {
    return 0.5f * x * (1.0f + erff(x * 0.70710678118654752440f));
}

template<int TRANSB, int EPI>
__global__ __launch_bounds__(256)
void sgemm_kernel(const float* __restrict__ A, const float* __restrict__ B,
                  const float* __restrict__ bias, const float* __restrict__ resid,
                  float* __restrict__ C,
                  int M, int N, int K,
                  long long sA, long long sB, long long sC,
                  float alpha)
{
    const int BM = 128, BN = 128, BK = 16;
    __shared__ float As[BK][BM];
    __shared__ float Bs[BK][BN];

    int batch = blockIdx.z;
    A += (long long)batch * sA;
    B += (long long)batch * sB;
    C += (long long)batch * sC;
    const float* Rp = resid ? resid + (long long)batch * sC : nullptr;

    int bm = blockIdx.y * BM;
    int bn = blockIdx.x * BN;
    int tid = threadIdx.x;
    int tm = (tid / 16) * 8;
    int tn = (tid % 16) * 8;

    float acc[8][8];
#pragma unroll
    for (int i = 0; i < 8; i++)
#pragma unroll
        for (int j = 0; j < 8; j++) acc[i][j] = 0.0f;

    for (int k0 = 0; k0 < K; k0 += BK) {
        // Load A tile (BM x BK), store transposed As[k][m]
#pragma unroll
        for (int i = tid; i < BM * (BK / 4); i += 256) {
            int r  = i / (BK / 4);
            int c4 = i % (BK / 4);
            float4 va = *(const float4*)&A[(long long)(bm + r) * K + k0 + c4 * 4];
            As[c4 * 4 + 0][r] = va.x;
            As[c4 * 4 + 1][r] = va.y;
            As[c4 * 4 + 2][r] = va.z;
            As[c4 * 4 + 3][r] = va.w;
        }
        if (!TRANSB) {
            // B tile rows k0..k0+15, cols bn..bn+127
#pragma unroll
            for (int i = tid; i < BK * (BN / 4); i += 256) {
                int r  = i / (BN / 4);
                int c4 = i % (BN / 4);
                int col = bn + c4 * 4;
                float4 vb = make_float4(0.f, 0.f, 0.f, 0.f);
                if (col < N) vb = *(const float4*)&B[(long long)(k0 + r) * N + col];
                *(float4*)&Bs[r][c4 * 4] = vb;
            }
        } else {
            // B is N x K; Bs[k][n] = B[bn+n][k0+k]
#pragma unroll
            for (int i = tid; i < BN * (BK / 4); i += 256) {
                int n  = i / (BK / 4);
                int c4 = i % (BK / 4);
                int col = bn + n;
                float4 vb = make_float4(0.f, 0.f, 0.f, 0.f);
                if (col < N) vb = *(const float4*)&B[(long long)col * K + k0 + c4 * 4];
                Bs[c4 * 4 + 0][n] = vb.x;
                Bs[c4 * 4 + 1][n] = vb.y;
                Bs[c4 * 4 + 2][n] = vb.z;
                Bs[c4 * 4 + 3][n] = vb.w;
            }
        }
        __syncthreads();

#pragma unroll
        for (int k = 0; k < BK; k++) {
            float a[8], b[8];
#pragma unroll
            for (int i = 0; i < 8; i++) a[i] = As[k][tm + i];
#pragma unroll
            for (int j = 0; j < 8; j++) b[j] = Bs[k][tn + j];
#pragma unroll
            for (int i = 0; i < 8; i++)
#pragma unroll
                for (int j = 0; j < 8; j++)
                    acc[i][j] = fmaf(a[i], b[j], acc[i][j]);
        }
        __syncthreads();
    }

    // Epilogue
#pragma unroll
    for (int i = 0; i < 8; i++) {
        long long row = bm + tm + i;
#pragma unroll
        for (int j = 0; j < 8; j += 4) {
            int col = bn + tn + j;
            if (col < N) {
                float4 o;
                float vals[4];
#pragma unroll
                for (int t = 0; t < 4; t++) {
                    float v = acc[i][j + t] * alpha;
                    if (EPI >= 1) v += bias[col + t];
                    if (EPI == 2) v += Rp[row * N + col + t];
                    if (EPI == 3) v = gelu_exact(v);
                    vals[t] = v;
                }
                o.x = vals[0]; o.y = vals[1]; o.z = vals[2]; o.w = vals[3];
                *(float4*)&C[row * N + col] = o;
            }
        }
    }
}

// ---------------------------- LayerNorm -------------------------------
__global__ __launch_bounds__(256)
void layernorm_kernel(const float* __restrict__ x, const float* __restrict__ gamma,
                      const float* __restrict__ beta, float* __restrict__ out)
{
    long long row = blockIdx.x;
    const float4* xr = (const float4*)(x + row * EMB);
    float4 v = xr[threadIdx.x];
    float s  = v.x + v.y + v.z + v.w;
    float ss = v.x * v.x + v.y * v.y + v.z * v.z + v.w * v.w;
#pragma unroll
    for (int o = 16; o; o >>= 1) {
        s  += __shfl_xor_sync(0xffffffffu, s,  o);
        ss += __shfl_xor_sync(0xffffffffu, ss, o);
    }
    __shared__ float sh_s[8], sh_ss[8];
    int w = threadIdx.x >> 5, l = threadIdx.x & 31;
    if (l == 0) { sh_s[w] = s; sh_ss[w] = ss; }
    __syncthreads();
    s = 0.f; ss = 0.f;
#pragma unroll
    for (int i = 0; i < 8; i++) { s += sh_s[i]; ss += sh_ss[i]; }
    float mu   = s * (1.0f / EMB);
    float var  = ss * (1.0f / EMB) - mu * mu;
    float rstd = rsqrtf(var + 1e-6f);
    float4 gv = ((const float4*)gamma)[threadIdx.x];
    float4 bv = ((const float4*)beta)[threadIdx.x];
    float4 o;
    o.x = (v.x - mu) * rstd * gv.x + bv.x;
    o.y = (v.y - mu) * rstd * gv.y + bv.y;
    o.z = (v.z - mu) * rstd * gv.z + bv.z;
    o.w = (v.w - mu) * rstd * gv.w + bv.w;
    ((float4*)(out + row * EMB))[threadIdx.x] = o;
}

// ---------------------------- Softmax (rows of 2048) -------------------
__global__ __launch_bounds__(256)
void softmax_kernel(float* __restrict__ S)
{
    long long row = blockIdx.x;
    float* p = S + row * SEQ;
    float4 v0 = ((float4*)p)[threadIdx.x];
    float4 v1 = ((float4*)p)[threadIdx.x + 256];

    float m = fmaxf(fmaxf(fmaxf(v0.x, v0.y), fmaxf(v0.z, v0.w)),
                    fmaxf(fmaxf(v1.x, v1.y), fmaxf(v1.z, v1.w)));
#pragma unroll
    for (int o = 16; o; o >>= 1) m = fmaxf(m, __shfl_xor_sync(0xffffffffu, m, o));
    __shared__ float sh[8];
    int w = threadIdx.x >> 5, l = threadIdx.x & 31;
    if (l == 0) sh[w] = m;
    __syncthreads();
    m = sh[0];
#pragma unroll
    for (int i = 1; i < 8; i++) m = fmaxf(m, sh[i]);
    __syncthreads();

    v0.x = expf(v0.x - m); v0.y = expf(v0.y - m); v0.z = expf(v0.z - m); v0.w = expf(v0.w - m);
    v1.x = expf(v1.x - m); v1.y = expf(v1.y - m); v1.z = expf(v1.z - m); v1.w = expf(v1.w - m);
    float s = v0.x + v0.y + v0.z + v0.w + v1.x + v1.y + v1.z + v1.w;
#pragma unroll
    for (int o = 16; o; o >>= 1) s += __shfl_xor_sync(0xffffffffu, s, o);
    if (l == 0) sh[w] = s;
    __syncthreads();
    s = 0.f;
#pragma unroll
    for (int i = 0; i < 8; i++) s += sh[i];
    float inv = 1.0f / s;
    v0.x *= inv; v0.y *= inv; v0.z *= inv; v0.w *= inv;
    v1.x *= inv; v1.y *= inv; v1.z *= inv; v1.w *= inv;
    ((float4*)p)[threadIdx.x]       = v0;
    ((float4*)p)[threadIdx.x + 256] = v1;
}

// ------------------- QKV split: (B,N,3,H,D) -> 3x (B*H,N,D) -------------
__global__ __launch_bounds__(256)
void split_qkv_kernel(const float* __restrict__ qkv,
                      float* __restrict__ q, float* __restrict__ k, float* __restrict__ v)
{
    long long idx = (long long)blockIdx.x * 256 + threadIdx.x;   // over TOK*EMB
    long long bn = idx / EMB;        // b*SEQ + n
    int c  = (int)(idx % EMB);
    long long b  = bn / SEQ;
    long long n  = bn % SEQ;
    int h  = c / HDIM;
    int d  = c % HDIM;
    long long src = bn * (3 * EMB) + (long long)h * HDIM + d;
    long long dst = ((b * NHEAD + h) * SEQ + n) * HDIM + d;
    q[dst] = qkv[src];
    k[dst] = qkv[src + EMB];
    v[dst] = qkv[src + 2 * EMB];
}

// ---------------- merge heads: (B,H,N,D) -> (B,N,H*D) -------------------
__global__ __launch_bounds__(256)
void merge_heads_kernel(const float* __restrict__ attn, float* __restrict__ out)
{
    long long idx = (long long)blockIdx.x * 256 + threadIdx.x;   // over TOK*EMB
    long long bn = idx / EMB;
    int c  = (int)(idx % EMB);
    long long b  = bn / SEQ;
    long long n  = bn % SEQ;
    int h  = c / HDIM;
    int d  = c % HDIM;
    long long src = ((b * NHEAD + h) * SEQ + n) * HDIM + d;
    out[idx] = attn[src];
}

// ---------------------------- host side --------------------------------
template<int TB, int EPI>
static void launch_gemm(const float* A, const float* B, const float* bias,
                        const float* resid, float* C,
                        int M, int N, int K, int batch,
                        long long sA, long long sB, long long sC, float alpha)
{
    dim3 grid((N + 127) / 128, (M + 127) / 128, batch);
    sgemm_kernel<TB, EPI><<<grid, 256>>>(A, B, bias, resid, C, M, N, K, sA, sB, sC, alpha);
}

extern "C" void kernel_launch(void* const* d_in, const int* in_sizes, int n_in,
                              void* d_out, int out_size)
{
    const float* x      = (const float*)d_in[0];
    const float* ln1_g  = (const float*)d_in[1];
    const float* ln1_b  = (const float*)d_in[2];
    const float* w_qkv  = (const float*)d_in[3];
    const float* b_qkv  = (const float*)d_in[4];
    const float* w_proj = (const float*)d_in[5];
    const float* b_proj = (const float*)d_in[6];
    const float* ln2_g  = (const float*)d_in[7];
    const float* ln2_b  = (const float*)d_in[8];
    const float* w_fc1  = (const float*)d_in[9];
    const float* b_fc1  = (const float*)d_in[10];
    const float* w_fc2  = (const float*)d_in[11];
    const float* b_fc2  = (const float*)d_in[12];
    float* out = (float*)d_out;

    float *ln1, *qkv, *q, *k, *v, *scores, *attn, *attnm, *x1, *ln2o, *hbuf;
    cudaGetSymbolAddress((void**)&ln1,    g_ln1);
    cudaGetSymbolAddress((void**)&qkv,    g_qkv);
    cudaGetSymbolAddress((void**)&q,      g_q);
    cudaGetSymbolAddress((void**)&k,      g_k);
    cudaGetSymbolAddress((void**)&v,      g_v);
    cudaGetSymbolAddress((void**)&scores, g_scores);
    cudaGetSymbolAddress((void**)&attn,   g_attn);
    cudaGetSymbolAddress((void**)&attnm,  g_attnm);
    cudaGetSymbolAddress((void**)&x1,     g_x1);
    cudaGetSymbolAddress((void**)&ln2o,   g_ln2);
    cudaGetSymbolAddress((void**)&hbuf,   g_h);

    // 1) LN1
    layernorm_kernel<<<TOK, 256>>>(x, ln1_g, ln1_b, ln1);

    // 2) QKV GEMM: [4096,1024] @ [1024,3072] + bias
    launch_gemm<0, 1>(ln1, w_qkv, b_qkv, nullptr, qkv, TOK, 3 * EMB, EMB, 1, 0, 0, 0, 1.0f);

    // 3) split heads
    split_qkv_kernel<<<(TOK * EMB) / 256, 256>>>(qkv, q, k, v);

    // 4) scores = Q K^T * scale  (batched 32, NT)
    launch_gemm<1, 0>(q, k, nullptr, nullptr, scores,
                      SEQ, SEQ, HDIM, BH,
                      (long long)SEQ * HDIM, (long long)SEQ * HDIM,
                      (long long)SEQ * SEQ, 0.125f);

    // 5) softmax over 65536 rows of 2048
    softmax_kernel<<<BH * SEQ, 256>>>(scores);

    // 6) attn = P @ V  (batched 32, NN)
    launch_gemm<0, 0>(scores, v, nullptr, nullptr, attn,
                      SEQ, HDIM, SEQ, BH,
                      (long long)SEQ * SEQ, (long long)SEQ * HDIM,
                      (long long)SEQ * HDIM, 1.0f);

    // 7) merge heads
    merge_heads_kernel<<<(TOK * EMB) / 256, 256>>>(attn, attnm);

    // 8) proj + residual: x1 = attnm @ w_proj + b_proj + x
    launch_gemm<0, 2>(attnm, w_proj, b_proj, x, x1, TOK, EMB, EMB, 1, 0, 0, 0, 1.0f);

    // 9) LN2
    layernorm_kernel<<<TOK, 256>>>(x1, ln2_g, ln2_b, ln2o);

    // 10) FC1 + GELU
    launch_gemm<0, 3>(ln2o, w_fc1, b_fc1, nullptr, hbuf, TOK, HIDDEN, EMB, 1, 0, 0, 0, 1.0f);

    // 11) FC2 + bias + residual -> out
    launch_gemm<0, 2>(hbuf, w_fc2, b_fc2, x1, out, TOK, EMB, HIDDEN, 1, 0, 0, 0, 1.0f);
}

// round 4
// speedup vs baseline: 2.3071x; 2.3071x over previous
#include <cuda_runtime.h>
#include <cuda_bf16.h>
#include <math.h>
#include <stdint.h>

// Problem constants
#define Bz     2
#define SEQ    2048
#define EMB    1024
#define NHEAD  16
#define HDIM   64
#define HIDDEN 4096
#define TOK    (Bz * SEQ)          // 4096 rows
#define BH     (Bz * NHEAD)        // 32 batched heads

typedef __nv_bfloat16 bf16;

// ===================== MMA primitives (non-'a' PTX, sm_80+) ============
__device__ __forceinline__ void ldm_x4(uint32_t* r, uint32_t addr) {
    asm volatile("ldmatrix.sync.aligned.m8n8.x4.shared.b16 {%0,%1,%2,%3}, [%4];"
        : "=r"(r[0]), "=r"(r[1]), "=r"(r[2]), "=r"(r[3]) : "r"(addr));
}
__device__ __forceinline__ void mma_bf16(float* c, const uint32_t* a,
                                         uint32_t b0, uint32_t b1) {
    asm volatile(
        "mma.sync.aligned.m16n8k16.row.col.f32.bf16.bf16.f32 "
        "{%0,%1,%2,%3}, {%4,%5,%6,%7}, {%8,%9}, {%0,%1,%2,%3};"
        : "+f"(c[0]), "+f"(c[1]), "+f"(c[2]), "+f"(c[3])
        : "r"(a[0]), "r"(a[1]), "r"(a[2]), "r"(a[3]), "r"(b0), "r"(b1));
}
__device__ __forceinline__ uint32_t smem_to_u32(const void* p) {
    uint32_t a;
    asm("{ .reg .u64 t; cvta.to.shared.u64 t, %1; cvt.u32.u64 %0, t; }" : "=r"(a) : "l"(p));
    return a;
}
#define SW128(off) ((off) ^ (((off) >> 3) & 0x70))

// ===================== scratch =========================================
__device__ bf16  g_wqkvT_h[3 * EMB * EMB],  g_wqkvT_l[3 * EMB * EMB];
__device__ bf16  g_wprojT_h[EMB * EMB],     g_wprojT_l[EMB * EMB];
__device__ bf16  g_wfc1T_h[HIDDEN * EMB],   g_wfc1T_l[HIDDEN * EMB];
__device__ bf16  g_wfc2T_h[EMB * HIDDEN],   g_wfc2T_l[EMB * HIDDEN];
__device__ bf16  g_ln1_h[TOK * EMB],        g_ln1_l[TOK * EMB];
__device__ float g_qkv[TOK * 3 * EMB];
__device__ bf16  g_q_h[BH * SEQ * HDIM],    g_q_l[BH * SEQ * HDIM];
__device__ bf16  g_k_h[BH * SEQ * HDIM],    g_k_l[BH * SEQ * HDIM];
__device__ bf16  g_vt_h[BH * HDIM * SEQ],   g_vt_l[BH * HDIM * SEQ];
__device__ float g_scores[(long long)BH * SEQ * SEQ];    // 512 MB
__device__ bf16  g_p_h[(long long)BH * SEQ * SEQ];       // 256 MB
__device__ bf16  g_p_l[(long long)BH * SEQ * SEQ];       // 256 MB
__device__ bf16  g_am_h[TOK * EMB],         g_am_l[TOK * EMB];
__device__ float g_x1[TOK * EMB];
__device__ bf16  g_ln2_h[TOK * EMB],        g_ln2_l[TOK * EMB];
__device__ bf16  g_h_h[TOK * HIDDEN],       g_h_l[TOK * HIDDEN];

__device__ __forceinline__ void bf16split(float v, bf16& hi, bf16& lo) {
    hi = __float2bfloat16(v);
    lo = __float2bfloat16(v - __bfloat162float(hi));
}
__device__ __forceinline__ float gelu_exact(float x) {
    return 0.5f * x * (1.0f + erff(x * 0.70710678118654752440f));
}

// ===================== mma.sync split-bf16 GEMM ========================
// D[M,N] = alpha * (A @ B^T)  A[M,K], B[N,K] as hi/lo bf16 (3-term product).
#define EPI_ALPHA      0
#define EPI_BIAS       1
#define EPI_BIAS_RES   2
#define EPI_SPLIT      3
#define EPI_GELU_SPLIT 4

template<int BN, int WM, int WN, int EPI>
__global__ __launch_bounds__(256, 1)
void gemm_mma(const bf16* __restrict__ Ahi, const bf16* __restrict__ Alo,
              const bf16* __restrict__ Bhi, const bf16* __restrict__ Blo,
              const float* __restrict__ bias, const float* __restrict__ resid,
              float* __restrict__ C, bf16* __restrict__ Chi, bf16* __restrict__ Clo,
              int M, int N, int K, int ldc,
              long long sA, long long sB,
              int hdiv, long long sCb, long long sCh,
              float alpha)
{
    constexpr int BK = 64;                       // bf16 per row = 128 bytes
    constexpr int OFF_AL = 128 * 128;
    constexpr int OFF_BH = 2 * 128 * 128;
    constexpr int OFF_BL = OFF_BH + BN * 128;
    constexpr int WGC = BN / WN;                 // warp grid cols
    constexpr int MT  = WM / 16;                 // m16 tiles per warp
    constexpr int NT  = WN / 8;                  // n8 tiles per warp
    constexpr int NG  = WN / 16;                 // n16 ldmatrix groups

    extern __shared__ char sm[];
    const uint32_t smb = smem_to_u32(sm);
    const int tid = threadIdx.x, wid = tid >> 5, lane = tid & 31;
    const int bm = blockIdx.y * 128, bn = blockIdx.x * BN, z = blockIdx.z;
    const int wm0 = (wid / WGC) * WM, wn0 = (wid % WGC) * WN;

    Ahi += (long long)z * sA;  Alo += (long long)z * sA;
    Bhi += (long long)z * sB;  Blo += (long long)z * sB;
    const long long coff = (long long)(z / hdiv) * sCb + (long long)(z % hdiv) * sCh;

    float acc[MT][NT][4];
#pragma unroll
    for (int i = 0; i < MT; i++)
#pragma unroll
        for (int j = 0; j < NT; j++)
#pragma unroll
            for (int t = 0; t < 4; t++) acc[i][j][t] = 0.0f;

    // per-thread ldmatrix row addressing (constant across chunks)
    const int swz   = lane & 7;
    const int aHalf = lane >> 4;                 // k-half for A
    const int bHalf = (lane >> 3) & 1;           // k-half for B
    int aRowOff[MT], bRowOff[NG];
#pragma unroll
    for (int mt = 0; mt < MT; mt++)
        aRowOff[mt] = (wm0 + mt * 16 + (lane & 15)) * 128;
#pragma unroll
    for (int ng = 0; ng < NG; ng++)
        bRowOff[ng] = (wn0 + ng * 16 + (lane & 7) + ((lane >> 4) << 3)) * 128;

    const int nch = K / BK;
    for (int c = 0; c < nch; c++) {
        const long long k0 = (long long)c * BK;
        {
            const bf16* a0 = Ahi + (long long)bm * K + k0;
            const bf16* a1 = Alo + (long long)bm * K + k0;
#pragma unroll
            for (int i = tid; i < 128 * 8; i += 256) {
                int r = i >> 3, u = i & 7;
                int sw = SW128(r * 128 + u * 16);
                *(int4*)(sm + sw)          = *(const int4*)(a0 + (long long)r * K + u * 8);
                *(int4*)(sm + OFF_AL + sw) = *(const int4*)(a1 + (long long)r * K + u * 8);
            }
            const bf16* b0 = Bhi + (long long)bn * K + k0;
            const bf16* b1 = Blo + (long long)bn * K + k0;
#pragma unroll
            for (int i = tid; i < BN * 8; i += 256) {
                int r = i >> 3, u = i & 7;
                int sw = SW128(r * 128 + u * 16);
                *(int4*)(sm + OFF_BH + sw) = *(const int4*)(b0 + (long long)r * K + u * 8);
                *(int4*)(sm + OFF_BL + sw) = *(const int4*)(b1 + (long long)r * K + u * 8);
            }
        }
        __syncthreads();

#pragma unroll
        for (int ks = 0; ks < BK / 16; ks++) {
            const uint32_t ca = (uint32_t)(((2 * ks + aHalf) ^ swz) * 16);
            const uint32_t cb = (uint32_t)(((2 * ks + bHalf) ^ swz) * 16);
            uint32_t ah[MT][4], al[MT][4], bhr[NG][4], blr[NG][4];
#pragma unroll
            for (int mt = 0; mt < MT; mt++) {
                ldm_x4(ah[mt], smb + aRowOff[mt] + ca);
                ldm_x4(al[mt], smb + OFF_AL + aRowOff[mt] + ca);
            }
#pragma unroll
            for (int ng = 0; ng < NG; ng++) {
                ldm_x4(bhr[ng], smb + OFF_BH + bRowOff[ng] + cb);
                ldm_x4(blr[ng], smb + OFF_BL + bRowOff[ng] + cb);
            }
            // pass 1: Ah * Bh
#pragma unroll
            for (int mt = 0; mt < MT; mt++)
#pragma unroll
                for (int nt = 0; nt < NT; nt++)
                    mma_bf16(acc[mt][nt], ah[mt],
                             bhr[nt >> 1][(nt & 1) * 2], bhr[nt >> 1][(nt & 1) * 2 + 1]);
            // pass 2: Ah * Bl
#pragma unroll
            for (int mt = 0; mt < MT; mt++)
#pragma unroll
                for (int nt = 0; nt < NT; nt++)
                    mma_bf16(acc[mt][nt], ah[mt],
                             blr[nt >> 1][(nt & 1) * 2], blr[nt >> 1][(nt & 1) * 2 + 1]);
            // pass 3: Al * Bh
#pragma unroll
            for (int mt = 0; mt < MT; mt++)
#pragma unroll
                for (int nt = 0; nt < NT; nt++)
                    mma_bf16(acc[mt][nt], al[mt],
                             bhr[nt >> 1][(nt & 1) * 2], bhr[nt >> 1][(nt & 1) * 2 + 1]);
        }
        __syncthreads();
    }

    // -------- epilogue straight from registers --------
#pragma unroll
    for (int mt = 0; mt < MT; mt++) {
#pragma unroll
        for (int half = 0; half < 2; half++) {
            const long long row = bm + wm0 + mt * 16 + (lane >> 2) + half * 8;
#pragma unroll
            for (int nt = 0; nt < NT; nt++) {
                const int col = bn + wn0 + nt * 8 + (lane & 3) * 2;
                float v0 = acc[mt][nt][half * 2 + 0] * alpha;
                float v1 = acc[mt][nt][half * 2 + 1] * alpha;
                if (EPI == EPI_BIAS || EPI == EPI_BIAS_RES || EPI == EPI_GELU_SPLIT) {
                    v0 += bias[col]; v1 += bias[col + 1];
                }
                if (EPI == EPI_BIAS_RES) {
                    const float* rp = resid + coff + row * (long long)ldc + col;
                    v0 += rp[0]; v1 += rp[1];
                }
                if (EPI == EPI_GELU_SPLIT) {
                    v0 = gelu_exact(v0); v1 = gelu_exact(v1);
                }
                const long long o = coff + row * (long long)ldc + col;
                if (EPI == EPI_ALPHA || EPI == EPI_BIAS || EPI == EPI_BIAS_RES) {
                    float2 w; w.x = v0; w.y = v1;
                    *(float2*)(C + o) = w;
                } else {
                    bf16 h0, l0, h1, l1;
                    bf16split(v0, h0, l0); bf16split(v1, h1, l1);
                    __nv_bfloat162 hh; hh.x = h0; hh.y = h1;
                    __nv_bfloat162 ll; ll.x = l0; ll.y = l1;
                    *(__nv_bfloat162*)(Chi + o) = hh;
                    *(__nv_bfloat162*)(Clo + o) = ll;
                }
            }
        }
    }
}

// ===================== LayerNorm -> bf16 hi/lo =========================
__global__ __launch_bounds__(256)
void layernorm_split_kernel(const float* __restrict__ x, const float* __restrict__ gamma,
                            const float* __restrict__ beta,
                            bf16* __restrict__ oh, bf16* __restrict__ ol)
{
    long long row = blockIdx.x;
    const float4* xr = (const float4*)(x + row * EMB);
    float4 v = xr[threadIdx.x];
    float s  = v.x + v.y + v.z + v.w;
    float ss = v.x * v.x + v.y * v.y + v.z * v.z + v.w * v.w;
#pragma unroll
    for (int o = 16; o; o >>= 1) {
        s  += __shfl_xor_sync(0xffffffffu, s,  o);
        ss += __shfl_xor_sync(0xffffffffu, ss, o);
    }
    __shared__ float sh_s[8], sh_ss[8];
    int w = threadIdx.x >> 5, l = threadIdx.x & 31;
    if (l == 0) { sh_s[w] = s; sh_ss[w] = ss; }
    __syncthreads();
    s = 0.f; ss = 0.f;
#pragma unroll
    for (int i = 0; i < 8; i++) { s += sh_s[i]; ss += sh_ss[i]; }
    float mu   = s * (1.0f / EMB);
    float var  = ss * (1.0f / EMB) - mu * mu;
    float rstd = rsqrtf(var + 1e-6f);
    float4 gv = ((const float4*)gamma)[threadIdx.x];
    float4 bv = ((const float4*)beta)[threadIdx.x];
    float o0 = (v.x - mu) * rstd * gv.x + bv.x;
    float o1 = (v.y - mu) * rstd * gv.y + bv.y;
    float o2 = (v.z - mu) * rstd * gv.z + bv.z;
    float o3 = (v.w - mu) * rstd * gv.w + bv.w;
    bf16 h0,l0,h1,l1,h2,l2,h3,l3;
    bf16split(o0,h0,l0); bf16split(o1,h1,l1); bf16split(o2,h2,l2); bf16split(o3,h3,l3);
    long long base = row * EMB + threadIdx.x * 4;
    __nv_bfloat162 a; a.x=h0; a.y=h1; __nv_bfloat162 b; b.x=h2; b.y=h3;
    __nv_bfloat162 c; c.x=l0; c.y=l1; __nv_bfloat162 d; d.x=l2; d.y=l3;
    *(__nv_bfloat162*)(oh + base)     = a;
    *(__nv_bfloat162*)(oh + base + 2) = b;
    *(__nv_bfloat162*)(ol + base)     = c;
    *(__nv_bfloat162*)(ol + base + 2) = d;
}

// ===================== Softmax -> bf16 hi/lo ===========================
__global__ __launch_bounds__(256)
void softmax_split_kernel(const float* __restrict__ S,
                          bf16* __restrict__ ph, bf16* __restrict__ pl)
{
    long long row = blockIdx.x;
    const float* p = S + row * SEQ;
    float4 v0 = ((const float4*)p)[threadIdx.x];
    float4 v1 = ((const float4*)p)[threadIdx.x + 256];

    float m = fmaxf(fmaxf(fmaxf(v0.x, v0.y), fmaxf(v0.z, v0.w)),
                    fmaxf(fmaxf(v1.x, v1.y), fmaxf(v1.z, v1.w)));
#pragma unroll
    for (int o = 16; o; o >>= 1) m = fmaxf(m, __shfl_xor_sync(0xffffffffu, m, o));
    __shared__ float sh[8];
    int w = threadIdx.x >> 5, l = threadIdx.x & 31;
    if (l == 0) sh[w] = m;
    __syncthreads();
    m = sh[0];
#pragma unroll
    for (int i = 1; i < 8; i++) m = fmaxf(m, sh[i]);
    __syncthreads();

    v0.x = expf(v0.x - m); v0.y = expf(v0.y - m); v0.z = expf(v0.z - m); v0.w = expf(v0.w - m);
    v1.x = expf(v1.x - m); v1.y = expf(v1.y - m); v1.z = expf(v1.z - m); v1.w = expf(v1.w - m);
    float s = v0.x + v0.y + v0.z + v0.w + v1.x + v1.y + v1.z + v1.w;
#pragma unroll
    for (int o = 16; o; o >>= 1) s += __shfl_xor_sync(0xffffffffu, s, o);
    if (l == 0) sh[w] = s;
    __syncthreads();
    s = 0.f;
#pragma unroll
    for (int i = 0; i < 8; i++) s += sh[i];
    float inv = 1.0f / s;

    float a[8] = {v0.x*inv, v0.y*inv, v0.z*inv, v0.w*inv,
                  v1.x*inv, v1.y*inv, v1.z*inv, v1.w*inv};
    long long b0 = row * SEQ + threadIdx.x * 4;
    long long b1 = row * SEQ + 1024 + threadIdx.x * 4;
#pragma unroll
    for (int g = 0; g < 2; g++) {
        long long base = g ? b1 : b0;
        bf16 h0,l0,h1,l1,h2,l2,h3,l3;
        bf16split(a[g*4+0],h0,l0); bf16split(a[g*4+1],h1,l1);
        bf16split(a[g*4+2],h2,l2); bf16split(a[g*4+3],h3,l3);
        __nv_bfloat162 x; x.x=h0; x.y=h1; __nv_bfloat162 y; y.x=h2; y.y=h3;
        __nv_bfloat162 u; u.x=l0; u.y=l1; __nv_bfloat162 t; t.x=l2; t.y=l3;
        *(__nv_bfloat162*)(ph + base)     = x;
        *(__nv_bfloat162*)(ph + base + 2) = y;
        *(__nv_bfloat162*)(pl + base)     = u;
        *(__nv_bfloat162*)(pl + base + 2) = t;
    }
}

// ============ transpose-convert: src fp32 [R,C] -> dst [C,R] hi/lo =====
__global__ __launch_bounds__(256)
void wt_prep_kernel(const float* __restrict__ src, int R, int C,
                    bf16* __restrict__ dh, bf16* __restrict__ dl)
{
    __shared__ float t[32][33];
    int c0 = blockIdx.x * 32, r0 = blockIdx.y * 32;
    int tx = threadIdx.x & 31, ty = threadIdx.x >> 5;
#pragma unroll
    for (int i = ty; i < 32; i += 8)
        t[i][tx] = src[(long long)(r0 + i) * C + c0 + tx];
    __syncthreads();
#pragma unroll
    for (int i = ty; i < 32; i += 8) {
        float v = t[tx][i];
        bf16 h, l; bf16split(v, h, l);
        long long o = (long long)(c0 + i) * R + r0 + tx;
        dh[o] = h; dl[o] = l;
    }
}

// ============ V^T prep: qkv -> vt hi/lo [BH, 64, 2048] =================
__global__ __launch_bounds__(256)
void vt_prep_kernel(const float* __restrict__ qkv, bf16* __restrict__ dh, bf16* __restrict__ dl)
{
    __shared__ float t[32][33];
    int bh = blockIdx.z, b = bh / NHEAD, h = bh % NHEAD;
    int n0 = blockIdx.x * 32, d0 = blockIdx.y * 32;
    int tx = threadIdx.x & 31, ty = threadIdx.x >> 5;
#pragma unroll
    for (int i = ty; i < 32; i += 8)
        t[i][tx] = qkv[((long long)(b * SEQ + n0 + i)) * (3 * EMB) + 2 * EMB + h * HDIM + d0 + tx];
    __syncthreads();
#pragma unroll
    for (int i = ty; i < 32; i += 8) {
        float v = t[tx][i];
        bf16 hh, ll; bf16split(v, hh, ll);
        long long o = ((long long)bh * HDIM + d0 + i) * SEQ + n0 + tx;
        dh[o] = hh; dl[o] = ll;
    }
}

// ============ Q/K prep: qkv -> q,k hi/lo [BH, 2048, 64] ================
__global__ __launch_bounds__(256)
void qk_prep_kernel(const float* __restrict__ qkv,
                    bf16* __restrict__ qh, bf16* __restrict__ ql,
                    bf16* __restrict__ kh, bf16* __restrict__ kl)
{
    long long idx4 = (long long)blockIdx.x * 256 + threadIdx.x;   // over TOK*EMB/4
    long long e  = idx4 * 4;
    long long bn = e / EMB;
    int c  = (int)(e % EMB);
    long long b  = bn / SEQ, n = bn % SEQ;
    int h = c / HDIM, d = c % HDIM;
    long long src = bn * (3 * EMB) + (long long)h * HDIM + d;
    long long dst = ((b * NHEAD + h) * SEQ + n) * HDIM + d;
    float4 q4 = *(const float4*)(qkv + src);
    float4 k4 = *(const float4*)(qkv + src + EMB);
    bf16 h0,l0,h1,l1,h2,l2,h3,l3;
    bf16split(q4.x,h0,l0); bf16split(q4.y,h1,l1); bf16split(q4.z,h2,l2); bf16split(q4.w,h3,l3);
    { __nv_bfloat162 a; a.x=h0; a.y=h1; __nv_bfloat162 bb; bb.x=h2; bb.y=h3;
      __nv_bfloat162 cc; cc.x=l0; cc.y=l1; __nv_bfloat162 dd; dd.x=l2; dd.y=l3;
      *(__nv_bfloat162*)(qh+dst)=a; *(__nv_bfloat162*)(qh+dst+2)=bb;
      *(__nv_bfloat162*)(ql+dst)=cc; *(__nv_bfloat162*)(ql+dst+2)=dd; }
    bf16split(k4.x,h0,l0); bf16split(k4.y,h1,l1); bf16split(k4.z,h2,l2); bf16split(k4.w,h3,l3);
    { __nv_bfloat162 a; a.x=h0; a.y=h1; __nv_bfloat162 bb; bb.x=h2; bb.y=h3;
      __nv_bfloat162 cc; cc.x=l0; cc.y=l1; __nv_bfloat162 dd; dd.x=l2; dd.y=l3;
      *(__nv_bfloat162*)(kh+dst)=a; *(__nv_bfloat162*)(kh+dst+2)=bb;
      *(__nv_bfloat162*)(kl+dst)=cc; *(__nv_bfloat162*)(kl+dst+2)=dd; }
}

// ===================== host side =======================================
template<int BN, int WM, int WN, int EPI>
static void launch_gemm(const bf16* Ahi, const bf16* Alo, const bf16* Bhi, const bf16* Blo,
                        const float* bias, const float* resid,
                        float* C, bf16* Chi, bf16* Clo,
                        int M, int N, int K, int ldc,
                        long long sA, long long sB,
                        int batch, int hdiv, long long sCb, long long sCh,
                        float alpha)
{
    constexpr int SMEM_BYTES = 2 * 128 * 128 + 2 * BN * 128;
    cudaFuncSetAttribute(gemm_mma<BN, WM, WN, EPI>,
                         cudaFuncAttributeMaxDynamicSharedMemorySize, SMEM_BYTES);
    dim3 grid(N / BN, M / 128, batch);
    gemm_mma<BN, WM, WN, EPI><<<grid, 256, SMEM_BYTES>>>(
        Ahi, Alo, Bhi, Blo, bias, resid, C, Chi, Clo,
        M, N, K, ldc, sA, sB, hdiv, sCb, sCh, alpha);
}

extern "C" void kernel_launch(void* const* d_in, const int* in_sizes, int n_in,
                              void* d_out, int out_size)
{
    const float* x      = (const float*)d_in[0];
    const float* ln1_g  = (const float*)d_in[1];
    const float* ln1_b  = (const float*)d_in[2];
    const float* w_qkv  = (const float*)d_in[3];
    const float* b_qkv  = (const float*)d_in[4];
    const float* w_proj = (const float*)d_in[5];
    const float* b_proj = (const float*)d_in[6];
    const float* ln2_g  = (const float*)d_in[7];
    const float* ln2_b  = (const float*)d_in[8];
    const float* w_fc1  = (const float*)d_in[9];
    const float* b_fc1  = (const float*)d_in[10];
    const float* w_fc2  = (const float*)d_in[11];
    const float* b_fc2  = (const float*)d_in[12];
    float* out = (float*)d_out;

    bf16 *wqkvTh, *wqkvTl, *wprojTh, *wprojTl, *wfc1Th, *wfc1Tl, *wfc2Th, *wfc2Tl;
    bf16 *ln1h, *ln1l, *qh, *ql, *kh, *kl, *vth, *vtl, *ph, *pl, *amh, *aml, *ln2h, *ln2l, *hh, *hl;
    float *qkv, *scores, *x1;
    cudaGetSymbolAddress((void**)&wqkvTh, g_wqkvT_h);  cudaGetSymbolAddress((void**)&wqkvTl, g_wqkvT_l);
    cudaGetSymbolAddress((void**)&wprojTh, g_wprojT_h); cudaGetSymbolAddress((void**)&wprojTl, g_wprojT_l);
    cudaGetSymbolAddress((void**)&wfc1Th, g_wfc1T_h);  cudaGetSymbolAddress((void**)&wfc1Tl, g_wfc1T_l);
    cudaGetSymbolAddress((void**)&wfc2Th, g_wfc2T_h);  cudaGetSymbolAddress((void**)&wfc2Tl, g_wfc2T_l);
    cudaGetSymbolAddress((void**)&ln1h, g_ln1_h);      cudaGetSymbolAddress((void**)&ln1l, g_ln1_l);
    cudaGetSymbolAddress((void**)&qkv, g_qkv);
    cudaGetSymbolAddress((void**)&qh, g_q_h);          cudaGetSymbolAddress((void**)&ql, g_q_l);
    cudaGetSymbolAddress((void**)&kh, g_k_h);          cudaGetSymbolAddress((void**)&kl, g_k_l);
    cudaGetSymbolAddress((void**)&vth, g_vt_h);        cudaGetSymbolAddress((void**)&vtl, g_vt_l);
    cudaGetSymbolAddress((void**)&scores, g_scores);
    cudaGetSymbolAddress((void**)&ph, g_p_h);          cudaGetSymbolAddress((void**)&pl, g_p_l);
    cudaGetSymbolAddress((void**)&amh, g_am_h);        cudaGetSymbolAddress((void**)&aml, g_am_l);
    cudaGetSymbolAddress((void**)&x1, g_x1);
    cudaGetSymbolAddress((void**)&ln2h, g_ln2_h);      cudaGetSymbolAddress((void**)&ln2l, g_ln2_l);
    cudaGetSymbolAddress((void**)&hh, g_h_h);          cudaGetSymbolAddress((void**)&hl, g_h_l);

    // 0) weight transpose-converts  W[K,N] -> Wt[N,K] hi/lo
    wt_prep_kernel<<<dim3(3 * EMB / 32, EMB / 32), 256>>>(w_qkv, EMB, 3 * EMB, wqkvTh, wqkvTl);
    wt_prep_kernel<<<dim3(EMB / 32, EMB / 32), 256>>>(w_proj, EMB, EMB, wprojTh, wprojTl);
    wt_prep_kernel<<<dim3(HIDDEN / 32, EMB / 32), 256>>>(w_fc1, EMB, HIDDEN, wfc1Th, wfc1Tl);
    wt_prep_kernel<<<dim3(EMB / 32, HIDDEN / 32), 256>>>(w_fc2, HIDDEN, EMB, wfc2Th, wfc2Tl);

    // 1) LN1 -> hi/lo
    layernorm_split_kernel<<<TOK, 256>>>(x, ln1_g, ln1_b, ln1h, ln1l);

    // 2) QKV: [4096,3072] = ln1 @ w_qkv + b  (fp32 out)
    launch_gemm<128, 64, 32, EPI_BIAS>(ln1h, ln1l, wqkvTh, wqkvTl, b_qkv, nullptr,
                                       qkv, nullptr, nullptr,
                                       TOK, 3 * EMB, EMB, 3 * EMB, 0, 0, 1, 1, 0, 0, 1.0f);

    // 3) Q/K gather + V transpose, split to bf16
    qk_prep_kernel<<<(TOK * EMB / 4) / 256, 256>>>(qkv, qh, ql, kh, kl);
    vt_prep_kernel<<<dim3(SEQ / 32, HDIM / 32, BH), 256>>>(qkv, vth, vtl);

    // 4) scores = 0.125 * Q K^T  (batched 32)
    launch_gemm<128, 64, 32, EPI_ALPHA>(qh, ql, kh, kl, nullptr, nullptr,
                                        scores, nullptr, nullptr,
                                        SEQ, SEQ, HDIM, SEQ,
                                        (long long)SEQ * HDIM, (long long)SEQ * HDIM,
                                        BH, 1, (long long)SEQ * SEQ, 0, 0.125f);

    // 5) softmax -> P hi/lo
    softmax_split_kernel<<<BH * SEQ, 256>>>(scores, ph, pl);

    // 6) attn = P @ V  -> merged heads, split bf16  (batched 32, N=64)
    launch_gemm<64, 32, 32, EPI_SPLIT>(ph, pl, vth, vtl, nullptr, nullptr,
                                       nullptr, amh, aml,
                                       SEQ, HDIM, SEQ, EMB,
                                       (long long)SEQ * SEQ, (long long)HDIM * SEQ,
                                       BH, NHEAD, (long long)SEQ * EMB, HDIM, 1.0f);

    // 7) proj + residual: x1 = attnm @ w_proj + b + x
    launch_gemm<128, 64, 32, EPI_BIAS_RES>(amh, aml, wprojTh, wprojTl, b_proj, x,
                                           x1, nullptr, nullptr,
                                           TOK, EMB, EMB, EMB, 0, 0, 1, 1, 0, 0, 1.0f);

    // 8) LN2 -> hi/lo
    layernorm_split_kernel<<<TOK, 256>>>(x1, ln2_g, ln2_b, ln2h, ln2l);

    // 9) FC1 + GELU -> h hi/lo
    launch_gemm<128, 64, 32, EPI_GELU_SPLIT>(ln2h, ln2l, wfc1Th, wfc1Tl, b_fc1, nullptr,
                                             nullptr, hh, hl,
                                             TOK, HIDDEN, EMB, HIDDEN, 0, 0, 1, 1, 0, 0, 1.0f);

    // 10) FC2 + bias + residual -> out
    launch_gemm<128, 64, 32, EPI_BIAS_RES>(hh, hl, wfc2Th, wfc2Tl, b_fc2, x1,
                                           out, nullptr, nullptr,
                                           TOK, EMB, HIDDEN, EMB, 0, 0, 1, 1, 0, 0, 1.0f);
}